// round 1
// baseline (speedup 1.0000x reference)
#include <cuda_runtime.h>

#define BB 16
#define CC 64
#define NN 2048
#define TQ 128
#define TM 128
#define SROW 129   // padded row stride for S: conflict-free column scans

// Scratch (no allocations allowed)
__device__ float g_xx[BB * NN];
__device__ int   g_idx[BB * NN * 8];

typedef unsigned long long ull;

__device__ __forceinline__ ull pack2(float lo, float hi) {
    ull r;
    asm("mov.b64 %0, {%1, %2};" : "=l"(r) : "f"(lo), "f"(hi));
    return r;
}
__device__ __forceinline__ ull fma2(ull a, ull b, ull c) {
    ull d;
    asm("fma.rn.f32x2 %0, %1, %2, %3;" : "=l"(d) : "l"(a), "l"(b), "l"(c));
    return d;
}
__device__ __forceinline__ float2 unpack2(ull a) {
    float2 f;
    asm("mov.b64 {%0, %1}, %2;" : "=f"(f.x), "=f"(f.y) : "l"(a));
    return f;
}

// ---------------------------------------------------------------------------
// Kernel 1: per-point squared norms  xx[b][n] = sum_c x[b,c,n]^2
// ---------------------------------------------------------------------------
__global__ void xx_kernel(const float* __restrict__ x) {
    int t = blockIdx.x * blockDim.x + threadIdx.x;   // 0 .. B*N-1
    int b = t >> 11;
    int n = t & (NN - 1);
    const float* p = x + b * CC * NN + n;
    float s = 0.f;
#pragma unroll
    for (int c = 0; c < CC; ++c) {
        float v = p[c * NN];
        s = fmaf(v, v, s);
    }
    g_xx[t] = s;
}

// ---------------------------------------------------------------------------
// Kernel 2: KNN top-8 (top-9 incl. self, drop rank 0)
// CTA: 128 queries x full m sweep. 256 threads, 8x8 register tiles, f32x2 FMA.
// Shared: Qs[64][128] | S[128][129] (first 32KB aliased as Ms[64][128]) | xxs[128]
// ---------------------------------------------------------------------------
__global__ void __launch_bounds__(256, 2) knn_kernel(const float* __restrict__ x) {
    extern __shared__ float sm[];
    float* Qs  = sm;                    // CC*TQ = 8192 floats
    float* S   = sm + CC * TQ;          // TQ*SROW = 16512 floats
    float* Ms  = S;                     // aliases first CC*TM = 8192 floats of S
    float* xxs = S + TQ * SROW;         // TM floats

    const int b     = blockIdx.y;
    const int qbase = blockIdx.x * TQ;
    const int tid   = threadIdx.x;
    const int ty    = tid >> 4;         // 0..15
    const int tx    = tid & 15;         // 0..15
    const float* xb = x + b * CC * NN;

    // Load query tile Qs[c][q]
    for (int i = tid; i < (CC * TQ) / 4; i += 256) {
        int c = (i * 4) / TQ;
        int q = (i * 4) % TQ;
        *(float4*)&Qs[c * TQ + q] = *(const float4*)&xb[c * NN + qbase + q];
    }

    float val9[9];
    int   idx9[9];
#pragma unroll
    for (int k = 0; k < 9; ++k) { val9[k] = -3.4e38f; idx9[k] = 0; }

    for (int mb = 0; mb < NN; mb += TM) {
        __syncthreads();   // Qs ready (iter 0) / previous scan done before Ms overwrite

        // Load candidate tile Ms[c][m] and its norms
        for (int i = tid; i < (CC * TM) / 4; i += 256) {
            int c = (i * 4) / TM;
            int m = (i * 4) % TM;
            *(float4*)&Ms[c * TM + m] = *(const float4*)&xb[c * NN + mb + m];
        }
        if (tid < TM) xxs[tid] = g_xx[b * NN + mb + tid];
        __syncthreads();

        // 128x128 dot-product tile, 8x8 per thread, packed f32x2 FMA
        ull acc[8][4];
#pragma unroll
        for (int i = 0; i < 8; ++i)
#pragma unroll
            for (int j = 0; j < 4; ++j) acc[i][j] = 0ull;

#pragma unroll 4
        for (int c = 0; c < CC; ++c) {
            float4 q0 = *(const float4*)&Qs[c * TQ + ty * 8];
            float4 q1 = *(const float4*)&Qs[c * TQ + ty * 8 + 4];
            float4 m0 = *(const float4*)&Ms[c * TM + tx * 8];
            float4 m1 = *(const float4*)&Ms[c * TM + tx * 8 + 4];
            ull mm[4];
            mm[0] = pack2(m0.x, m0.y);
            mm[1] = pack2(m0.z, m0.w);
            mm[2] = pack2(m1.x, m1.y);
            mm[3] = pack2(m1.z, m1.w);
            float qv[8] = {q0.x, q0.y, q0.z, q0.w, q1.x, q1.y, q1.z, q1.w};
#pragma unroll
            for (int i = 0; i < 8; ++i) {
                ull qq = pack2(qv[i], qv[i]);
#pragma unroll
                for (int j = 0; j < 4; ++j) acc[i][j] = fma2(qq, mm[j], acc[i][j]);
            }
        }
        __syncthreads();   // compute done; safe to overwrite Ms region with S

        // Spill tile to shared (padded stride)
#pragma unroll
        for (int i = 0; i < 8; ++i) {
            int q = ty * 8 + i;
#pragma unroll
            for (int j = 0; j < 4; ++j) {
                float2 f = unpack2(acc[i][j]);
                S[q * SROW + tx * 8 + j * 2]     = f.x;
                S[q * SROW + tx * 8 + j * 2 + 1] = f.y;
            }
        }
        __syncthreads();

        // Top-9 update: one thread per query, stable (lowest-index tie-break)
        if (tid < TQ) {
            const float* srow = &S[tid * SROW];
            for (int m = 0; m < TM; ++m) {
                float v = fmaf(2.f, srow[m], -xxs[m]);
                if (v > val9[8]) {
                    val9[8] = v;
                    idx9[8] = mb + m;
#pragma unroll
                    for (int k = 8; k > 0; --k) {
                        if (val9[k] > val9[k - 1]) {
                            float tv = val9[k]; val9[k] = val9[k - 1]; val9[k - 1] = tv;
                            int   ti = idx9[k]; idx9[k] = idx9[k - 1]; idx9[k - 1] = ti;
                        }
                    }
                }
            }
        }
    }

    if (tid < TQ) {
        int q = qbase + tid;
#pragma unroll
        for (int k = 0; k < 8; ++k) g_idx[(b * NN + q) * 8 + k] = idx9[k + 1];
    }
}

// ---------------------------------------------------------------------------
// Kernel 3: output assembly
// out[b,c,n]   = x[b,c,n]
// out[b,c,N+n] = mean_k x[b,c,idx[b,n,k]]
// ---------------------------------------------------------------------------
__global__ void gather_kernel(const float* __restrict__ x, float* __restrict__ out) {
    __shared__ float row[NN];
    int b = blockIdx.x >> 6;
    int c = blockIdx.x & 63;
    const float* xr = x + (b * CC + c) * NN;
    for (int n = threadIdx.x; n < NN; n += blockDim.x) row[n] = xr[n];
    __syncthreads();
    const int* gi = g_idx + b * NN * 8;
    float* o = out + (size_t)(b * CC + c) * (2 * NN);
    for (int n = threadIdx.x; n < NN; n += blockDim.x) {
        o[n] = row[n];
        const int* gn = gi + n * 8;
        float s = 0.f;
#pragma unroll
        for (int k = 0; k < 8; ++k) s += row[gn[k]];
        o[NN + n] = s * 0.125f;
    }
}

// ---------------------------------------------------------------------------
extern "C" void kernel_launch(void* const* d_in, const int* in_sizes, int n_in,
                              void* d_out, int out_size) {
    (void)in_sizes; (void)n_in; (void)out_size;
    const float* x = (const float*)d_in[0];
    float* out = (float*)d_out;

    xx_kernel<<<(BB * NN) / 256, 256>>>(x);

    size_t smem = (size_t)(CC * TQ + TQ * SROW + TM) * sizeof(float);  // 99328 B
    cudaFuncSetAttribute(knn_kernel, cudaFuncAttributeMaxDynamicSharedMemorySize,
                         (int)smem);
    knn_kernel<<<dim3(NN / TQ, BB), 256, smem>>>(x);

    gather_kernel<<<BB * CC, 256>>>(x, out);
}